// round 11
// baseline (speedup 1.0000x reference)
#include <cuda_runtime.h>

#define BATCH   16
#define SLICES  37               // 16*37 = 592 = 148 SMs * 4 blocks -> co-resident
#define TPB     256
#define GRID    (BATCH * SLICES)
#define STRIDE  (SLICES * TPB)   // quad stride per segment sweep
#define EPSV    1e-5f

// Global scratch (allocation-free: __device__ arrays)
__device__ float              g_sum[BATCH * 16];
__device__ float              g_ssq[BATCH * 16];
__device__ int                g_start[BATCH + 1];
__device__ unsigned long long g_bar;   // monotonic across graph replays

// Grid-wide barrier: monotonic counter, replay-safe (no reset needed).
// Safe because GRID (592) blocks are guaranteed co-resident at
// __launch_bounds__(TPB, 4) on 148 SMs.
__device__ __forceinline__ void grid_barrier() {
    __syncthreads();
    if (threadIdx.x == 0) {
        __threadfence();
        unsigned long long old = atomicAdd(&g_bar, 1ULL);
        unsigned long long target = old - (old % (unsigned long long)GRID)
                                  + (unsigned long long)GRID;
        unsigned long long cur;
        do {
            asm volatile("ld.acquire.gpu.u64 %0, [%1];"
                         : "=l"(cur) : "l"(&g_bar) : "memory");
        } while (cur < target);
    }
    __syncthreads();
}

__global__ void __launch_bounds__(TPB, 4)
ogn_fused_kernel(const float4* __restrict__ data4,
                 const int*    __restrict__ batch_id,
                 const float*  __restrict__ weights,
                 const float*  __restrict__ bias,
                 float4*       __restrict__ out4,
                 int nrows) {
    const int t     = threadIdx.x;
    const int g     = t & 15;
    const int b     = blockIdx.x & 15;      // GRID is a multiple of 16
    const int slice = blockIdx.x >> 4;

    // ---- Phase A: zero accumulators + boundary scan (loop-free-ish) ----
    if (blockIdx.x == 0) {
        g_sum[t] = 0.f;                      // TPB == 256 == BATCH*16
        g_ssq[t] = 0.f;
        if (t == 0) {
            g_start[0] = 0;
            int bfirst = __ldg(&batch_id[0]);
            for (int v = 1; v <= bfirst; v++) g_start[v] = 0;           // leading empties
            int blast = __ldg(&batch_id[nrows - 1]);
            for (int v = blast + 1; v <= BATCH; v++) g_start[v] = nrows; // trailing empties
        }
    }
    {
        const int tid = blockIdx.x * TPB + t;
        for (int i0 = tid * 4; i0 < nrows - 1; i0 += GRID * TPB * 4) {
            if (i0 + 4 < nrows) {            // fast path: int4 + scalar edge
                int4 v = __ldg(&((const int4*)batch_id)[i0 >> 2]);
                int e0 = v.x, e1 = v.y, e2 = v.z, e3 = v.w;
                int e4 = __ldg(&batch_id[i0 + 4]);
                if (e0 != e1) for (int x = e0 + 1; x <= e1; x++) g_start[x] = i0 + 1;
                if (e1 != e2) for (int x = e1 + 1; x <= e2; x++) g_start[x] = i0 + 2;
                if (e2 != e3) for (int x = e2 + 1; x <= e3; x++) g_start[x] = i0 + 3;
                if (e3 != e4) for (int x = e3 + 1; x <= e4; x++) g_start[x] = i0 + 4;
            } else {                         // ragged tail
                for (int i = i0; i < nrows - 1; i++) {
                    int a = __ldg(&batch_id[i]);
                    int c = __ldg(&batch_id[i + 1]);
                    if (a != c) for (int x = a + 1; x <= c; x++) g_start[x] = i + 1;
                }
            }
        }
    }

    grid_barrier();

    // ---- Phase B: per-(batch, group) sum / sum-of-squares (R9's loop) ----
    const int r0 = __ldcg(&g_start[b]);
    const int r1 = __ldcg(&g_start[b + 1]);
    {
        const int qlim = r1 * 16;
        int qi = r0 * 16 + slice * TPB + t;

        float s0 = 0.f, s1 = 0.f, qa = 0.f, qb = 0.f;
        #pragma unroll 4
        for (; qi + STRIDE < qlim; qi += 2 * STRIDE) {
            float4 va = data4[qi];
            float4 vb = data4[qi + STRIDE];
            s0 += (va.x + va.y) + (va.z + va.w);
            qa += va.x * va.x + va.y * va.y + va.z * va.z + va.w * va.w;
            s1 += (vb.x + vb.y) + (vb.z + vb.w);
            qb += vb.x * vb.x + vb.y * vb.y + vb.z * vb.z + vb.w * vb.w;
        }
        if (qi < qlim) {                     // at most one straggler
            float4 v = data4[qi];
            s0 += (v.x + v.y) + (v.z + v.w);
            qa += v.x * v.x + v.y * v.y + v.z * v.z + v.w * v.w;
        }
        float gsum = s0 + s1;
        float gssq = qa + qb;

        // lanes t and t+16 in each warp share g: fold, then cross-warp.
        gsum += __shfl_xor_sync(0xffffffffu, gsum, 16);
        gssq += __shfl_xor_sync(0xffffffffu, gssq, 16);

        __shared__ float sh_sum[8][16];
        __shared__ float sh_ssq[8][16];
        const int w = t >> 5;
        if ((t & 31) < 16) { sh_sum[w][g] = gsum; sh_ssq[w][g] = gssq; }
        __syncthreads();

        if (t < 16) {
            float s = 0.f, q = 0.f;
            #pragma unroll
            for (int i = 0; i < 8; i++) { s += sh_sum[i][t]; q += sh_ssq[i][t]; }
            if (s != 0.f || q != 0.f) {
                atomicAdd(&g_sum[b * 16 + t], s);
                atomicAdd(&g_ssq[b * 16 + t], q);
            }
        }
    }

    grid_barrier();

    // ---- Phase C: stats -> register affine, reverse-sweep normalize ----
    __shared__ float smean[16], sistd[16];
    if (t < 16) {
        float n = (float)(r1 - r0);
        float inv_count = 1.f / (n * 4.f + EPSV);
        float s = __ldcg(&g_sum[b * 16 + t]);
        float q = __ldcg(&g_ssq[b * 16 + t]);
        float m = s * inv_count;
        float var = (q - 2.f * m * s + 4.f * n * m * m) * inv_count;
        smean[t] = m;
        sistd[t] = rsqrtf(var + EPSV);
    }
    __syncthreads();

    const float4 w4  = __ldg(&((const float4*)weights)[g]);
    const float4 bi4 = __ldg(&((const float4*)bias)[g]);
    const float istd = sistd[g];
    const float m    = smean[g];
    float4 a, bb;
    a.x = istd * w4.x;  a.y = istd * w4.y;  a.z = istd * w4.z;  a.w = istd * w4.w;
    bb.x = bi4.x - m * a.x;  bb.y = bi4.y - m * a.y;
    bb.z = bi4.z - m * a.z;  bb.w = bi4.w - m * a.w;

    const int base = r0 * 16 + slice * TPB + t;
    const int span = r1 * 16 - base;
    if (span > 0) {
        const int kmax = (span + STRIDE - 1) / STRIDE;
        #pragma unroll 4
        for (int k = kmax - 1; k >= 0; --k) {   // reverse: consume hot L2 tail first
            const int qi = base + k * STRIDE;
            float4 v = __ldcs(&data4[qi]);
            float4 o;
            o.x = fmaf(v.x, a.x, bb.x);
            o.y = fmaf(v.y, a.y, bb.y);
            o.z = fmaf(v.z, a.z, bb.z);
            o.w = fmaf(v.w, a.w, bb.w);
            __stcs(&out4[qi], o);
        }
    }
}

extern "C" void kernel_launch(void* const* d_in, const int* in_sizes, int n_in,
                              void* d_out, int out_size) {
    const float* data     = (const float*)d_in[0];
    const int*   batch_id = (const int*)d_in[1];
    const float* weights  = (const float*)d_in[2];
    const float* bias     = (const float*)d_in[3];
    float*       out      = (float*)d_out;
    const int    nrows    = in_sizes[1];          // batch_id element count = N

    ogn_fused_kernel<<<GRID, TPB>>>((const float4*)data, batch_id,
                                    weights, bias, (float4*)out, nrows);
}

// round 12
// speedup vs baseline: 1.1636x; 1.1636x over previous
#include <cuda_runtime.h>

#define BATCH   16
#define EPSV    1e-5f
#define SLICES  74               // 16*74 = 1184 = 148 SMs * 8 blocks: ONE exact wave
#define TPB     256
#define STRIDE  (SLICES * TPB)   // quad stride per segment sweep

// Global scratch (allocation-free: __device__ arrays)
__device__ float g_sum[BATCH * 16];
__device__ float g_ssq[BATCH * 16];
__device__ int   g_start[BATCH + 1]; // segment starts in sorted batch_id

// Setup: zero accumulators + boundary detection on the sorted batch_id.
// Loop-free per thread: one int4 load (4 ids) + one scalar edge load, all
// independent -> no loop-carried scoreboard drain.
__global__ void ogn_setup_kernel(const int* __restrict__ batch_id, int nrows) {
    const int t   = threadIdx.x;
    const int tid = blockIdx.x * blockDim.x + t;

    if (blockIdx.x == 0) {
        g_sum[t] = 0.f;                      // TPB == 256 == BATCH*16
        g_ssq[t] = 0.f;
        if (t == 0) {
            g_start[0] = 0;
            int bfirst = __ldg(&batch_id[0]);
            for (int v = 1; v <= bfirst; v++) g_start[v] = 0;           // leading empties
            int blast = __ldg(&batch_id[nrows - 1]);
            for (int v = blast + 1; v <= BATCH; v++) g_start[v] = nrows; // trailing empties
        }
    }

    const int i0 = tid * 4;                  // this thread's 4-element window
    if (i0 >= nrows - 1) return;

    int e[5];
    if (i0 + 4 < nrows) {                    // fast path: int4 + scalar edge
        int4 v = __ldg(&((const int4*)batch_id)[tid]);
        e[0] = v.x; e[1] = v.y; e[2] = v.z; e[3] = v.w;
        e[4] = __ldg(&batch_id[i0 + 4]);
        #pragma unroll
        for (int j = 0; j < 4; j++) {
            if (e[j] != e[j + 1]) {
                for (int v2 = e[j] + 1; v2 <= e[j + 1]; v2++) g_start[v2] = i0 + j + 1;
            }
        }
    } else {                                 // ragged tail (nrows not mult of 4)
        for (int i = i0; i < nrows - 1; i++) {
            int a = __ldg(&batch_id[i]);
            int b = __ldg(&batch_id[i + 1]);
            if (a != b) {
                for (int v2 = a + 1; v2 <= b; v2++) g_start[v2] = i + 1;
            }
        }
    }
}

// Pass 1: per-(batch, group) sum / sum-of-squares.
// Single-wave geometry (1184 blocks @ 8/SM), segment-aligned strided FORWARD
// sweep (leaves each segment's tail hot in L2 for pass2's reverse sweep).
// Two independent load+FMA chains, unroll 2 (MLP depth shown non-binding in
// R10; keeps regs <= 32 for the 8-blocks/SM guarantee).
__global__ void __launch_bounds__(TPB, 8)
ogn_pass1_kernel(const float4* __restrict__ data4) {
    const int t     = threadIdx.x;
    const int g     = t & 15;
    const int b     = blockIdx.x & (BATCH - 1);
    const int slice = blockIdx.x >> 4;

    const int q1 = g_start[b + 1] * 16;
    int qi = g_start[b] * 16 + slice * TPB + t;

    float s0 = 0.f, s1 = 0.f, qa = 0.f, qb = 0.f;
    #pragma unroll 2
    for (; qi + STRIDE < q1; qi += 2 * STRIDE) {
        float4 va = data4[qi];
        float4 vb = data4[qi + STRIDE];
        s0 += (va.x + va.y) + (va.z + va.w);
        qa += va.x * va.x + va.y * va.y + va.z * va.z + va.w * va.w;
        s1 += (vb.x + vb.y) + (vb.z + vb.w);
        qb += vb.x * vb.x + vb.y * vb.y + vb.z * vb.z + vb.w * vb.w;
    }
    if (qi < q1) {                      // at most one straggler
        float4 v = data4[qi];
        s0 += (v.x + v.y) + (v.z + v.w);
        qa += v.x * v.x + v.y * v.y + v.z * v.z + v.w * v.w;
    }
    float gsum = s0 + s1;
    float gssq = qa + qb;

    // lanes t and t+16 in each warp share g: fold, then cross-warp via shared.
    gsum += __shfl_xor_sync(0xffffffffu, gsum, 16);
    gssq += __shfl_xor_sync(0xffffffffu, gssq, 16);

    __shared__ float sh_sum[8][16];
    __shared__ float sh_ssq[8][16];
    const int w = t >> 5;
    if ((t & 31) < 16) { sh_sum[w][g] = gsum; sh_ssq[w][g] = gssq; }
    __syncthreads();

    if (t < 16) {
        float s = 0.f, q = 0.f;
        #pragma unroll
        for (int i = 0; i < 8; i++) { s += sh_sum[i][t]; q += sh_ssq[i][t]; }
        if (s != 0.f || q != 0.f) {
            atomicAdd(&g_sum[b * 16 + t], s);
            atomicAdd(&g_ssq[b * 16 + t], q);
        }
    }
}

// Pass 2: out = x * A[b][c] + B[b][c].
// Single-wave geometry. Inline per-block stats -> register A/B, then a
// REVERSE sweep of this segment so the lines pass1 just left in L2 are
// consumed first. __ldcs/__stcs keep both streams evict-first.
__global__ void __launch_bounds__(TPB, 8)
ogn_pass2_kernel(const float4* __restrict__ data4,
                 float4* __restrict__ out4,
                 const float* __restrict__ weights,
                 const float* __restrict__ bias) {
    __shared__ float smean[16], sistd[16];
    const int t     = threadIdx.x;
    const int g     = t & 15;
    const int b     = blockIdx.x & (BATCH - 1);
    const int slice = blockIdx.x >> 4;

    const int r0 = g_start[b];
    const int r1 = g_start[b + 1];

    if (t < 16) {
        float n = (float)(r1 - r0);
        float inv_count = 1.f / (n * 4.f + EPSV);
        float s = g_sum[b * 16 + t], q = g_ssq[b * 16 + t];
        float m = s * inv_count;
        float var = (q - 2.f * m * s + 4.f * n * m * m) * inv_count;
        smean[t] = m;
        sistd[t] = rsqrtf(var + EPSV);
    }
    __syncthreads();

    const float4 w4  = __ldg(&((const float4*)weights)[g]);
    const float4 bi4 = __ldg(&((const float4*)bias)[g]);
    const float istd = sistd[g];
    const float m    = smean[g];
    float4 a, bb;
    a.x = istd * w4.x;  a.y = istd * w4.y;  a.z = istd * w4.z;  a.w = istd * w4.w;
    bb.x = bi4.x - m * a.x;  bb.y = bi4.y - m * a.y;
    bb.z = bi4.z - m * a.z;  bb.w = bi4.w - m * a.w;

    const int base = r0 * 16 + slice * TPB + t;
    const int span = r1 * 16 - base;
    if (span > 0) {
        const int kmax = (span + STRIDE - 1) / STRIDE;
        #pragma unroll 2
        for (int k = kmax - 1; k >= 0; --k) {   // reverse: consume hot L2 tail first
            const int qi = base + k * STRIDE;
            float4 v = __ldcs(&data4[qi]);
            float4 o;
            o.x = fmaf(v.x, a.x, bb.x);
            o.y = fmaf(v.y, a.y, bb.y);
            o.z = fmaf(v.z, a.z, bb.z);
            o.w = fmaf(v.w, a.w, bb.w);
            __stcs(&out4[qi], o);
        }
    }
}

extern "C" void kernel_launch(void* const* d_in, const int* in_sizes, int n_in,
                              void* d_out, int out_size) {
    const float* data     = (const float*)d_in[0];
    const int*   batch_id = (const int*)d_in[1];
    const float* weights  = (const float*)d_in[2];
    const float* bias     = (const float*)d_in[3];
    float*       out      = (float*)d_out;
    const int    nrows    = in_sizes[1];          // batch_id element count = N

    const int setup_blocks = (nrows / 4 + TPB - 1) / TPB + 1;  // ~1025 for N=1M
    ogn_setup_kernel<<<setup_blocks, TPB>>>(batch_id, nrows);
    ogn_pass1_kernel<<<BATCH * SLICES, TPB>>>((const float4*)data);
    ogn_pass2_kernel<<<BATCH * SLICES, TPB>>>((const float4*)data, (float4*)out,
                                              weights, bias);
}